// round 2
// baseline (speedup 1.0000x reference)
#include <cuda_runtime.h>
#include <math.h>

// Problem constants (fixed by dataset)
#define NMAX 10000
#define EMAX 160000
#define ETOT (EMAX + NMAX)
#define NEG_SLOPE 0.2f
#define GAT_EPS 1e-16f

// ---------------- device scratch (static, no allocation) ----------------
__device__ int      g_deg[NMAX];
__device__ int      g_rowstart[NMAX + 1];
__device__ int      g_ctr[NMAX];
__device__ unsigned g_csr[ETOT];            // src | (maskedBit<<31)
__device__ __align__(16) float g_h1[NMAX * 64];
__device__ float    g_as1[NMAX * 8];
__device__ float    g_ad1[NMAX * 8];
__device__ __align__(16) float g_h1a[NMAX * 64];       // elu(gat1 out)
__device__ __align__(16) float g_h2[NMAX * 1024];
__device__ float    g_as2[NMAX * 8];
__device__ float    g_ad2[NMAX * 8];

// ---------------- CSR build ----------------
__global__ void k_init(int N) {
    int i = blockIdx.x * blockDim.x + threadIdx.x;
    if (i < N) g_deg[i] = 1;   // one appended self-loop per node
}

__global__ void k_count(const int* __restrict__ ei, int E, int N) {
    int i = blockIdx.x * blockDim.x + threadIdx.x;
    if (i < E) {
        int d = ei[E + i];
        if ((unsigned)d < (unsigned)N) atomicAdd(&g_deg[d], 1);
    }
}

__global__ void k_scan(int N) {
    __shared__ int buf[1024];
    __shared__ int carry;
    int tid = threadIdx.x;
    if (tid == 0) carry = 0;
    __syncthreads();
    for (int base = 0; base < N; base += 1024) {
        int i = base + tid;
        int v = (i < N) ? g_deg[i] : 0;
        buf[tid] = v;
        __syncthreads();
        for (int off = 1; off < 1024; off <<= 1) {
            int t = (tid >= off) ? buf[tid - off] : 0;
            __syncthreads();
            buf[tid] += t;
            __syncthreads();
        }
        int c = carry;
        int incl = buf[tid] + c;
        if (i < N) {
            g_rowstart[i] = incl - v;   // exclusive prefix
            g_ctr[i]      = incl - v;
        }
        __syncthreads();
        if (tid == 1023) carry = buf[1023] + c;
        __syncthreads();
    }
    if (tid == 0) g_rowstart[N] = carry;
}

__global__ void k_fill(const int* __restrict__ ei, int E, int N) {
    int i = blockIdx.x * blockDim.x + threadIdx.x;
    if (i < E) {
        int s = ei[i];
        int d = ei[E + i];
        if ((unsigned)s >= (unsigned)N || (unsigned)d >= (unsigned)N) return;
        unsigned ent = (unsigned)s | ((s == d) ? 0x80000000u : 0u);
        int pos = atomicAdd(&g_ctr[d], 1);
        g_csr[pos] = ent;
    } else if (i < E + N) {
        int nd = i - E;
        int pos = atomicAdd(&g_ctr[nd], 1);
        g_csr[pos] = (unsigned)nd;   // appended self loop, mask=1
    }
}

// ---------------- layer 1 ----------------
// h1 = x @ W1   (N x 128 @ 128 x 64)
__global__ void k_gemm1(const float* __restrict__ x, const float* __restrict__ W1, int N) {
    int col  = threadIdx.x & 63;
    int rs   = threadIdx.x >> 6;
    int row0 = blockIdx.x * 16 + rs * 4;
    const float* xp0 = x + (size_t)min(row0 + 0, N - 1) * 128;
    const float* xp1 = x + (size_t)min(row0 + 1, N - 1) * 128;
    const float* xp2 = x + (size_t)min(row0 + 2, N - 1) * 128;
    const float* xp3 = x + (size_t)min(row0 + 3, N - 1) * 128;
    float a0 = 0.f, a1 = 0.f, a2 = 0.f, a3 = 0.f;
    #pragma unroll 4
    for (int k = 0; k < 128; k++) {
        float w = W1[k * 64 + col];
        a0 = fmaf(xp0[k], w, a0);
        a1 = fmaf(xp1[k], w, a1);
        a2 = fmaf(xp2[k], w, a2);
        a3 = fmaf(xp3[k], w, a3);
    }
    if (row0 + 0 < N) g_h1[(size_t)(row0 + 0) * 64 + col] = a0;
    if (row0 + 1 < N) g_h1[(size_t)(row0 + 1) * 64 + col] = a1;
    if (row0 + 2 < N) g_h1[(size_t)(row0 + 2) * 64 + col] = a2;
    if (row0 + 3 < N) g_h1[(size_t)(row0 + 3) * 64 + col] = a3;
}

__global__ void k_attn1(const float* __restrict__ asw, const float* __restrict__ adw, int N) {
    int i = blockIdx.x * blockDim.x + threadIdx.x;
    if (i >= N * 8) return;
    int n = i >> 3, h = i & 7;
    const float* hp = g_h1 + (size_t)n * 64 + h * 8;
    float s = 0.f, d = 0.f;
    #pragma unroll
    for (int c = 0; c < 8; c++) {
        float v = hp[c];
        s = fmaf(v, asw[h * 8 + c], s);
        d = fmaf(v, adw[h * 8 + c], d);
    }
    g_as1[i] = s;
    g_ad1[i] = d;
}

// one warp per node: softmax attention + message aggregation + bias + ELU
__global__ void k_agg1(const float* __restrict__ b1, int N) {
    int gw = (blockIdx.x * blockDim.x + threadIdx.x) >> 5;
    int lane = threadIdx.x & 31;
    if (gw >= N) return;
    int n = gw;
    int row = g_rowstart[n];
    int deg = g_deg[n];
    int myh = lane >> 2;           // lane handles cols 2*lane,2*lane+1; head = (2*lane)/8
    float myM = 0.f, myS = 1.f;
    #pragma unroll
    for (int h = 0; h < 8; h++) {
        float adh = g_ad1[n * 8 + h];
        float m = -INFINITY, s = 0.f;
        for (int base = 0; base < deg; base += 32) {
            int j = base + lane;
            float e = -INFINITY, msk = 0.f;
            if (j < deg) {
                unsigned ent = g_csr[row + j];
                int src = (int)(ent & 0x7fffffffu);
                msk = (ent & 0x80000000u) ? 0.f : 1.f;
                float t = g_as1[src * 8 + h] + adh;
                e = t > 0.f ? t : NEG_SLOPE * t;
            }
            float cm = e;
            #pragma unroll
            for (int o = 16; o > 0; o >>= 1) cm = fmaxf(cm, __shfl_xor_sync(0xffffffffu, cm, o));
            float ex = (j < deg) ? __expf(e - cm) * msk : 0.f;
            #pragma unroll
            for (int o = 16; o > 0; o >>= 1) ex += __shfl_xor_sync(0xffffffffu, ex, o);
            if (cm > m) { s = s * __expf(m - cm) + ex; m = cm; }
            else        { s += ex * __expf(cm - m); }
        }
        if (h == myh) { myM = m; myS = s + GAT_EPS; }
    }
    int c0 = lane * 2;
    float adh = g_ad1[n * 8 + myh];
    float a0 = 0.f, a1 = 0.f;
    for (int j = 0; j < deg; j++) {
        unsigned ent = g_csr[row + j];
        if (ent & 0x80000000u) continue;
        int src = (int)ent;
        float t = g_as1[src * 8 + myh] + adh;
        float e = t > 0.f ? t : NEG_SLOPE * t;
        float w = __expf(e - myM) / myS;
        float2 v = *(const float2*)(g_h1 + (size_t)src * 64 + c0);
        a0 = fmaf(v.x, w, a0);
        a1 = fmaf(v.y, w, a1);
    }
    float o0 = a0 + b1[c0], o1 = a1 + b1[c0 + 1];
    o0 = o0 > 0.f ? o0 : (__expf(o0) - 1.f);   // ELU
    o1 = o1 > 0.f ? o1 : (__expf(o1) - 1.f);
    *(float2*)(g_h1a + (size_t)n * 64 + c0) = make_float2(o0, o1);
}

// ---------------- layer 2 ----------------
// h2 = h1a @ W2   (N x 64 @ 64 x 1024).  Tile: 16 rows x 128 cols per block (128 thr).
__global__ void k_gemm2(const float* __restrict__ W2, int N) {
    __shared__ float As[16][64];
    int tid = threadIdx.x;
    int row0 = blockIdx.x * 16;
    for (int i = tid; i < 16 * 16; i += 128) {
        int r = i >> 4, q = i & 15;
        int rr = min(row0 + r, N - 1);
        ((float4*)As[r])[q] = ((const float4*)(g_h1a + (size_t)rr * 64))[q];
    }
    __syncthreads();
    int cg = blockIdx.y * 128 + tid;
    float acc[16];
    #pragma unroll
    for (int r = 0; r < 16; r++) acc[r] = 0.f;
    #pragma unroll
    for (int k = 0; k < 64; k += 4) {
        float w0 = W2[(k + 0) * 1024 + cg];
        float w1 = W2[(k + 1) * 1024 + cg];
        float w2 = W2[(k + 2) * 1024 + cg];
        float w3 = W2[(k + 3) * 1024 + cg];
        #pragma unroll
        for (int r = 0; r < 16; r++) {
            float4 a = *(const float4*)&As[r][k];
            acc[r] = fmaf(a.x, w0, acc[r]);
            acc[r] = fmaf(a.y, w1, acc[r]);
            acc[r] = fmaf(a.z, w2, acc[r]);
            acc[r] = fmaf(a.w, w3, acc[r]);
        }
    }
    #pragma unroll
    for (int r = 0; r < 16; r++) {
        int rr = row0 + r;
        if (rr < N) g_h2[(size_t)rr * 1024 + cg] = acc[r];
    }
}

// one warp per (node, head): dot h2[n,h,:] with a_src2/a_dst2
__global__ void k_attn2(const float* __restrict__ asw, const float* __restrict__ adw, int N) {
    int gw = (blockIdx.x * blockDim.x + threadIdx.x) >> 5;
    int lane = threadIdx.x & 31;
    if (gw >= N * 8) return;
    int n = gw >> 3, h = gw & 7;
    float4 v  = ((const float4*)(g_h2 + (size_t)n * 1024 + h * 128))[lane];
    float4 sa = ((const float4*)(asw + h * 128))[lane];
    float4 da = ((const float4*)(adw + h * 128))[lane];
    float s = v.x * sa.x + v.y * sa.y + v.z * sa.z + v.w * sa.w;
    float d = v.x * da.x + v.y * da.y + v.z * da.z + v.w * da.w;
    #pragma unroll
    for (int o = 16; o > 0; o >>= 1) {
        s += __shfl_xor_sync(0xffffffffu, s, o);
        d += __shfl_xor_sync(0xffffffffu, d, o);
    }
    if (lane == 0) { g_as2[gw] = s; g_ad2[gw] = d; }
}

// one block per node: attention softmax + 1024-wide aggregation + bias + log_softmax
__global__ void k_agg2(const float* __restrict__ b2, float* __restrict__ out, int N) {
    __shared__ float s_m[8], s_d[8], s_ad[8];
    __shared__ float s_w[32 * 8];
    __shared__ int   s_src[32];
    __shared__ float red[256];
    int n = blockIdx.x;
    int tid = threadIdx.x, lane = tid & 31, wid = tid >> 5;
    int row = g_rowstart[n], deg = g_deg[n];
    if (tid < 8) s_ad[tid] = g_ad2[n * 8 + tid];
    __syncthreads();

    // phase A: warp `wid` computes per-head max/denominator (online softmax)
    {
        float adh = s_ad[wid];
        float m = -INFINITY, s = 0.f;
        for (int base = 0; base < deg; base += 32) {
            int j = base + lane;
            float e = -INFINITY, msk = 0.f;
            if (j < deg) {
                unsigned ent = g_csr[row + j];
                int src = (int)(ent & 0x7fffffffu);
                msk = (ent & 0x80000000u) ? 0.f : 1.f;
                float t = g_as2[src * 8 + wid] + adh;
                e = t > 0.f ? t : NEG_SLOPE * t;
            }
            float cm = e;
            #pragma unroll
            for (int o = 16; o > 0; o >>= 1) cm = fmaxf(cm, __shfl_xor_sync(0xffffffffu, cm, o));
            float ex = (j < deg) ? __expf(e - cm) * msk : 0.f;
            #pragma unroll
            for (int o = 16; o > 0; o >>= 1) ex += __shfl_xor_sync(0xffffffffu, ex, o);
            if (cm > m) { s = s * __expf(m - cm) + ex; m = cm; }
            else        { s += ex * __expf(cm - m); }
        }
        if (lane == 0) { s_m[wid] = m; s_d[wid] = s + GAT_EPS; }
    }
    __syncthreads();

    // phase B: accumulate messages; thread owns 4 contiguous cols (head == wid)
    int c0 = tid * 4;
    float adh = s_ad[wid];
    float4 acc = make_float4(0.f, 0.f, 0.f, 0.f);
    for (int base = 0; base < deg; base += 32) {
        int cnt = min(32, deg - base);
        __syncthreads();   // protect smem reuse across chunks
        if (lane < cnt) {
            unsigned ent = g_csr[row + base + lane];
            int src = (int)(ent & 0x7fffffffu);
            float msk = (ent & 0x80000000u) ? 0.f : 1.f;
            float t = g_as2[src * 8 + wid] + adh;
            float e = t > 0.f ? t : NEG_SLOPE * t;
            s_w[lane * 8 + wid] = __expf(e - s_m[wid]) / s_d[wid] * msk;
            if (wid == 0) s_src[lane] = src;
        }
        __syncthreads();
        #pragma unroll 4
        for (int j = 0; j < cnt; j++) {
            float w = s_w[j * 8 + wid];
            if (w != 0.f) {   // warp-uniform: skips masked edges without divergence
                const float4 v = *(const float4*)(g_h2 + (size_t)s_src[j] * 1024 + c0);
                acc.x = fmaf(v.x, w, acc.x);
                acc.y = fmaf(v.y, w, acc.y);
                acc.z = fmaf(v.z, w, acc.z);
                acc.w = fmaf(v.w, w, acc.w);
            }
        }
    }

    // bias + log_softmax over 1024 (block reduce)
    float x0 = acc.x + b2[c0 + 0];
    float x1 = acc.y + b2[c0 + 1];
    float x2 = acc.z + b2[c0 + 2];
    float x3 = acc.w + b2[c0 + 3];
    float tm = fmaxf(fmaxf(x0, x1), fmaxf(x2, x3));
    red[tid] = tm;
    __syncthreads();
    for (int s = 128; s > 0; s >>= 1) {
        if (tid < s) red[tid] = fmaxf(red[tid], red[tid + s]);
        __syncthreads();
    }
    float bmax = red[0];
    __syncthreads();
    float te = __expf(x0 - bmax) + __expf(x1 - bmax) + __expf(x2 - bmax) + __expf(x3 - bmax);
    red[tid] = te;
    __syncthreads();
    for (int s = 128; s > 0; s >>= 1) {
        if (tid < s) red[tid] += red[tid + s];
        __syncthreads();
    }
    float lse = bmax + logf(red[0]);
    float4 o = make_float4(x0 - lse, x1 - lse, x2 - lse, x3 - lse);
    *(float4*)(out + (size_t)n * 1024 + c0) = o;
}

// ---------------- launcher ----------------
extern "C" void kernel_launch(void* const* d_in, const int* in_sizes, int n_in,
                              void* d_out, int out_size) {
    const float* x   = (const float*)d_in[0];
    const int*   ei  = (const int*)d_in[1];    // edge_index: int32 (JAX default, no x64)
    const float* W1  = (const float*)d_in[2];
    const float* aS1 = (const float*)d_in[3];
    const float* aD1 = (const float*)d_in[4];
    const float* b1  = (const float*)d_in[5];
    const float* W2  = (const float*)d_in[6];
    const float* aS2 = (const float*)d_in[7];
    const float* aD2 = (const float*)d_in[8];
    const float* b2  = (const float*)d_in[9];
    float*       out = (float*)d_out;

    int N = in_sizes[0] / 128;
    int E = in_sizes[1] / 2;

    k_init <<<(N + 255) / 256, 256>>>(N);
    k_count<<<(E + 255) / 256, 256>>>(ei, E, N);
    k_scan <<<1, 1024>>>(N);
    k_fill <<<(E + N + 255) / 256, 256>>>(ei, E, N);

    k_gemm1<<<(N + 15) / 16, 256>>>(x, W1, N);
    k_attn1<<<(N * 8 + 255) / 256, 256>>>(aS1, aD1, N);
    k_agg1 <<<(N * 32 + 255) / 256, 256>>>(b1, N);

    dim3 g2((N + 15) / 16, 8);
    k_gemm2<<<g2, 128>>>(W2, N);
    k_attn2<<<(N * 8 * 32 + 255) / 256, 256>>>(aS2, aD2, N);
    k_agg2 <<<N, 256>>>(b2, out, N);
}